// round 2
// baseline (speedup 1.0000x reference)
#include <cuda_runtime.h>

// SparseAttention: QK^T -> entmax(alpha=1.5, 100-iter bisection) -> @V
// B=8, S=2048, D=128, fp32.
//
// Key algorithmic fact: final tau >= z_max - 1, so only keys with
// z = 0.5*score > z_max - 1 can ever have nonzero weight (~2-5 per row).
// We fuse: tiled fp32 QK^T + streaming candidate collection + per-row
// bisection over candidates only + sparse PV gather.

#define BATCH   8
#define SEQ     2048
#define DIM     128
#define MQ      64            // query rows per CTA
#define NK      128           // key cols per tile
#define KTILES  (SEQ / NK)    // 16
#define CAP     128           // candidate capacity per row
#define NITER   100
#define TAUMAX_OFF 0.02209708691f   // float32(2048^(-0.5))

__global__ __launch_bounds__(256, 1)
void entmax_attn_kernel(const float* __restrict__ Qg,
                        const float* __restrict__ Kg,
                        const float* __restrict__ Vg,
                        float* __restrict__ Og)
{
    extern __shared__ float sm[];
    float* sQT  = sm;                          // [DIM][MQ]  transposed Q tile
    float* sKT  = sQT + DIM * MQ;              // [DIM][NK]  transposed K tile
    float* sZ   = sKT + DIM * NK;              // [MQ][NK]   z tile (0.5*score)
    float* cz   = sZ + MQ * NK;                // [MQ][CAP]  candidate z
    int*   cix  = (int*)(cz + MQ * CAP);       // [MQ][CAP]  candidate key index
    float* rmax = (float*)(cix + MQ * CAP);    // [MQ] running z max
    int*   rcnt = (int*)(rmax + MQ);           // [MQ] candidate count

    const int tid  = threadIdx.x;
    const int tx   = tid & 15;      // 16
    const int ty   = tid >> 4;      // 16
    const int lane = tid & 31;
    const int wid  = tid >> 5;      // 8 warps
    const int b    = blockIdx.y;
    const int q0   = blockIdx.x * MQ;

    // ---- Load Q tile, transposed into [d][q] ----
    {
        const float4* Q4 = (const float4*)(Qg + (size_t)(b * SEQ + q0) * DIM);
        #pragma unroll
        for (int i = tid; i < MQ * (DIM / 4); i += 256) {
            int q = i & (MQ - 1);
            int c = i >> 6;                    // d-chunk 0..31
            float4 v = Q4[q * (DIM / 4) + c];
            sQT[(4 * c + 0) * MQ + q] = v.x;
            sQT[(4 * c + 1) * MQ + q] = v.y;
            sQT[(4 * c + 2) * MQ + q] = v.z;
            sQT[(4 * c + 3) * MQ + q] = v.w;
        }
    }
    if (tid < MQ) { rmax[tid] = -3.0e38f; rcnt[tid] = 0; }
    __syncthreads();

    // ---- Main loop over key tiles ----
    for (int kt = 0; kt < KTILES; kt++) {
        const int k0 = kt * NK;

        // Load K tile, transposed into [d][k]
        const float4* K4 = (const float4*)(Kg + (size_t)(b * SEQ + k0) * DIM);
        for (int i = tid; i < NK * (DIM / 4); i += 256) {
            int k = i & (NK - 1);
            int c = i >> 7;                    // d-chunk 0..31
            float4 v = K4[k * (DIM / 4) + c];
            sKT[(4 * c + 0) * NK + k] = v.x;
            sKT[(4 * c + 1) * NK + k] = v.y;
            sKT[(4 * c + 2) * NK + k] = v.z;
            sKT[(4 * c + 3) * NK + k] = v.w;
        }
        __syncthreads();

        // Register-tiled GEMM: each thread computes 4 q-rows x 8 k-cols
        float acc[4][8];
        #pragma unroll
        for (int i = 0; i < 4; i++)
            #pragma unroll
            for (int j = 0; j < 8; j++) acc[i][j] = 0.0f;

        #pragma unroll 8
        for (int d = 0; d < DIM; d++) {
            float4 qv = *(const float4*)&sQT[d * MQ + ty * 4];
            float4 ka = *(const float4*)&sKT[d * NK + tx * 8];
            float4 kb = *(const float4*)&sKT[d * NK + tx * 8 + 4];
            float qq[4] = {qv.x, qv.y, qv.z, qv.w};
            float kk[8] = {ka.x, ka.y, ka.z, ka.w, kb.x, kb.y, kb.z, kb.w};
            #pragma unroll
            for (int i = 0; i < 4; i++)
                #pragma unroll
                for (int j = 0; j < 8; j++)
                    acc[i][j] += qq[i] * kk[j];
        }

        // Write z tile (z = (alpha-1)*score = 0.5*score)
        #pragma unroll
        for (int i = 0; i < 4; i++)
            #pragma unroll
            for (int j = 0; j < 8; j++)
                sZ[(ty * 4 + i) * NK + tx * 8 + j] = 0.5f * acc[i][j];
        __syncthreads();

        // Candidate scan: each warp owns rows wid, wid+8, ...
        for (int r = wid; r < MQ; r += 8) {
            float vv[4];
            #pragma unroll
            for (int j = 0; j < 4; j++) vv[j] = sZ[r * NK + lane * 4 + j];
            float m = fmaxf(fmaxf(vv[0], vv[1]), fmaxf(vv[2], vv[3]));
            #pragma unroll
            for (int o = 16; o > 0; o >>= 1)
                m = fmaxf(m, __shfl_xor_sync(0xffffffffu, m, o));
            float nm  = fmaxf(rmax[r], m);
            float thr = nm - 1.0f;
            int cnt = rcnt[r];
            #pragma unroll
            for (int j = 0; j < 4; j++) {
                bool p = vv[j] > thr;
                unsigned msk = __ballot_sync(0xffffffffu, p);
                int pos = cnt + __popc(msk & ((1u << lane) - 1u));
                if (p && pos < CAP) {
                    cz[r * CAP + pos]  = vv[j];
                    cix[r * CAP + pos] = k0 + lane * 4 + j;
                }
                cnt = min(cnt + __popc(msk), CAP);
            }
            // lazy compaction against the improved running max (rare)
            if (cnt > 96) {
                if (lane == 0) {
                    int w2 = 0;
                    for (int t = 0; t < cnt; t++) {
                        float zz = cz[r * CAP + t];
                        if (zz > thr) {
                            cz[r * CAP + w2]  = zz;
                            cix[r * CAP + w2] = cix[r * CAP + t];
                            w2++;
                        }
                    }
                    cnt = w2;
                }
                cnt = __shfl_sync(0xffffffffu, cnt, 0);
            }
            if (lane == 0) { rmax[r] = nm; rcnt[r] = cnt; }
        }
        __syncthreads();
    }

    // ---- Bisection: one row per thread (threads 0..63) ----
    if (tid < MQ) {
        const int r = tid;
        const float zmax = rmax[r];
        const float thr  = zmax - 1.0f;
        const int cnt = rcnt[r];
        // final compaction against the global max
        int c2 = 0;
        for (int t = 0; t < cnt; t++) {
            float zz = cz[r * CAP + t];
            if (zz > thr) {
                cz[r * CAP + c2]  = zz;
                cix[r * CAP + c2] = cix[r * CAP + t];
                c2++;
            }
        }
        float tmin = thr;
        float tmax = zmax - TAUMAX_OFF;
        float tau = 0.5f * (tmin + tmax);
        float Zs  = 1.0f;

        float zr[16];
        const bool inreg = (c2 <= 16);
        if (inreg) {
            #pragma unroll
            for (int t = 0; t < 16; t++)
                zr[t] = (t < c2) ? cz[r * CAP + t] : -3.0e38f;
        }
        for (int it = 0; it < NITER; it++) {
            tau = 0.5f * (tmin + tmax);
            float z = 0.0f;
            if (inreg) {
                #pragma unroll
                for (int t = 0; t < 16; t++) {
                    float p = fmaxf(zr[t] - tau, 0.0f);
                    z = fmaf(p, p, z);
                }
            } else {
                for (int t = 0; t < c2; t++) {
                    float p = fmaxf(cz[r * CAP + t] - tau, 0.0f);
                    z = fmaf(p, p, z);
                }
            }
            Zs = z;
            if (z >= 1.0f) tmin = tau; else tmax = tau;
        }
        // weights from last-iter tau (faithful to reference)
        const float invZ = 1.0f / Zs;
        for (int t = 0; t < c2; t++) {
            float zz = inreg ? zr[t] : cz[r * CAP + t];
            float p = fmaxf(zz - tau, 0.0f);
            cz[r * CAP + t] = p * p * invZ;
        }
        rcnt[r] = c2;
    }
    __syncthreads();

    // ---- Sparse PV gather: warp per row, lane covers 4 dims ----
    {
        const float4* V4 = (const float4*)(Vg + (size_t)b * SEQ * DIM);
        float4* O4 = (float4*)(Og + (size_t)(b * SEQ + q0) * DIM);
        for (int r = wid; r < MQ; r += 8) {
            int cnt = rcnt[r];
            float4 acc = make_float4(0.f, 0.f, 0.f, 0.f);
            for (int t = 0; t < cnt; t++) {
                float w = cz[r * CAP + t];
                int ki  = cix[r * CAP + t];
                float4 vv = V4[ki * (DIM / 4) + lane];
                acc.x = fmaf(w, vv.x, acc.x);
                acc.y = fmaf(w, vv.y, acc.y);
                acc.z = fmaf(w, vv.z, acc.z);
                acc.w = fmaf(w, vv.w, acc.w);
            }
            O4[r * (DIM / 4) + lane] = acc;
        }
    }
}

extern "C" void kernel_launch(void* const* d_in, const int* in_sizes, int n_in,
                              void* d_out, int out_size)
{
    const float* Q = (const float*)d_in[0];
    const float* K = (const float*)d_in[1];
    const float* V = (const float*)d_in[2];
    float* O = (float*)d_out;

    const size_t smem =
        (size_t)(DIM * MQ + DIM * NK + MQ * NK + MQ * CAP) * sizeof(float) +
        (size_t)(MQ * CAP) * sizeof(int) +
        (size_t)MQ * sizeof(float) + (size_t)MQ * sizeof(int);

    cudaFuncSetAttribute(entmax_attn_kernel,
                         cudaFuncAttributeMaxDynamicSharedMemorySize,
                         (int)smem);

    dim3 grid(SEQ / MQ, BATCH);   // (32, 8)
    entmax_attn_kernel<<<grid, 256, smem>>>(Q, K, V, O);
}

// round 4
// speedup vs baseline: 2.6101x; 2.6101x over previous
#include <cuda_runtime.h>
#include <cuda_bf16.h>
#include <cstdint>

// SparseAttention: QK^T -> entmax(alpha=1.5, 100-iter bisection) -> @V
// B=8, S=2048, D=128 fp32.
//
// Round 3: ldmatrix + mma.sync bf16 (hi/lo split, 3 products, fp32 accum) for
// the score GEMM — portable to plain compute_103 (no tcgen05).
// Warp tile = 16 query rows x 128 keys, so each query row lives in one
// lane-quad: candidate collection (z > runmax-1) happens straight off the
// MMA accumulator fragments. Exact bisection over candidates + sparse PV.

#define BATCH   8
#define SEQ     2048
#define DIM     128
#define MQ      128
#define NTILES  16
#define CAP     24
#define CAPP    25
#define NITER   100
#define TAUMAX_OFF 0.02209708691f   // float32(2048^-0.5)

// ---- smem layout (bytes) ----
#define S_QHI   0                   // 32768: Q hi, swizzled [128][128] bf16
#define S_QLO   32768               // 32768: Q lo
#define S_K     65536               // 2 bufs x (hi 32768 + lo 32768) = 131072
#define S_CZ    196608              // float cz[128][CAPP] = 12800
#define S_CIX   209408              // int   cix[128][CAPP] = 12800
#define S_RMX   222208              // float rmax[128]
#define S_CNT   222720              // int   cnt[128]
#define SMEM_TOTAL 223232

__device__ __forceinline__ uint32_t smem_u32(const void* p) {
    uint32_t a;
    asm("{ .reg .u64 t; cvta.to.shared.u64 t, %1; cvt.u32.u64 %0, t; }"
        : "=r"(a) : "l"(p));
    return a;
}

__device__ __forceinline__ void ldsm4(uint32_t* r, uint32_t addr) {
    asm volatile("ldmatrix.sync.aligned.m8n8.x4.shared.b16 {%0,%1,%2,%3}, [%4];"
                 : "=r"(r[0]), "=r"(r[1]), "=r"(r[2]), "=r"(r[3]) : "r"(addr));
}

__device__ __forceinline__ void mma_bf16(float* d, const uint32_t* a,
                                         uint32_t b0, uint32_t b1) {
    asm volatile(
        "mma.sync.aligned.m16n8k16.row.col.f32.bf16.bf16.f32 "
        "{%0,%1,%2,%3}, {%4,%5,%6,%7}, {%8,%9}, {%0,%1,%2,%3};"
        : "+f"(d[0]), "+f"(d[1]), "+f"(d[2]), "+f"(d[3])
        : "r"(a[0]), "r"(a[1]), "r"(a[2]), "r"(a[3]), "r"(b0), "r"(b1));
}

// 8 fp32 -> packed bf16 hi (uint4) + bf16 lo (uint4)
__device__ __forceinline__ void cvt8(const float4& v0, const float4& v1,
                                     uint4& uh, uint4& ul) {
    float x[8] = {v0.x, v0.y, v0.z, v0.w, v1.x, v1.y, v1.z, v1.w};
    uint32_t h[8], l[8];
    #pragma unroll
    for (int j = 0; j < 8; j++) {
        __nv_bfloat16 hb = __float2bfloat16(x[j]);
        float r = x[j] - __bfloat162float(hb);
        __nv_bfloat16 lb = __float2bfloat16(r);
        h[j] = (uint32_t)__bfloat16_as_ushort(hb);
        l[j] = (uint32_t)__bfloat16_as_ushort(lb);
    }
    uh.x = h[0] | (h[1] << 16); uh.y = h[2] | (h[3] << 16);
    uh.z = h[4] | (h[5] << 16); uh.w = h[6] | (h[7] << 16);
    ul.x = l[0] | (l[1] << 16); ul.y = l[2] | (l[3] << 16);
    ul.z = l[4] | (l[5] << 16); ul.w = l[6] | (l[7] << 16);
}

__global__ __launch_bounds__(256, 1)
void attn_kernel(const float* __restrict__ Qg, const float* __restrict__ Kg,
                 const float* __restrict__ Vg, float* __restrict__ Og)
{
    extern __shared__ unsigned char sm[];
    const uint32_t sbase = smem_u32(sm);
    const int tid  = threadIdx.x;
    const int lane = tid & 31;
    const int w    = tid >> 5;          // 8 warps
    const int b    = blockIdx.y;
    const int qt   = blockIdx.x;

    // ---- prologue: stage Q tile and K tile 0 (fp32 -> bf16 hi/lo, swizzled) ----
    {
        const float* qsrc = Qg + ((size_t)b * SEQ + (size_t)qt * MQ) * DIM;
        const float* ksrc = Kg + (size_t)b * SEQ * DIM;
        #pragma unroll
        for (int p = 0; p < 8; p++) {
            int gidx = p * 256 + tid;
            int row = gidx >> 4, c16 = gidx & 15;
            uint32_t off = (uint32_t)row * 256 + (((uint32_t)c16 ^ (row & 7)) << 4);
            const float4* gp = (const float4*)(qsrc + row * DIM + c16 * 8);
            uint4 uh, ul;
            cvt8(gp[0], gp[1], uh, ul);
            *(uint4*)(sm + S_QHI + off) = uh;
            *(uint4*)(sm + S_QLO + off) = ul;
            gp = (const float4*)(ksrc + row * DIM + c16 * 8);
            cvt8(gp[0], gp[1], uh, ul);
            *(uint4*)(sm + S_K + off) = uh;
            *(uint4*)(sm + S_K + 32768 + off) = ul;
        }
    }
    __syncthreads();

    // per-lane ldmatrix address terms
    const int g  = lane >> 2;           // row group within warp quad
    const int q  = lane & 3;            // lane within quad
    const int rterm = (((lane >> 3) & 1) << 3) + (lane & 7);
    const int hib = lane >> 4;
    const int xr  = lane & 7;
    const uint32_t aHbase = sbase + S_QHI + (uint32_t)(w * 16 + rterm) * 256;
    const uint32_t aLbase = sbase + S_QLO + (uint32_t)(w * 16 + rterm) * 256;
    const uint32_t kLane  = sbase + S_K + (uint32_t)rterm * 256;

    float* czf  = (float*)(sm + S_CZ);
    int*   cixp = (int*)(sm + S_CIX);
    float* srmx = (float*)(sm + S_RMX);
    int*   scnt = (int*)(sm + S_CNT);

    const int row0 = w * 16 + g, row1 = row0 + 8;
    float rmax0 = -3.0e38f, rmax1 = -3.0e38f;
    int cnt0 = 0, cnt1 = 0;

    for (int t = 0; t < NTILES; t++) {
        // ---- prefetch next K tile (global -> regs) ----
        float4 sv[16];
        if (t + 1 < NTILES) {
            const float* ksrc = Kg + ((size_t)b * SEQ + (size_t)(t + 1) * 128) * DIM;
            #pragma unroll
            for (int p = 0; p < 8; p++) {
                int gidx = p * 256 + tid;
                int row = gidx >> 4, c16 = gidx & 15;
                const float4* gp = (const float4*)(ksrc + row * DIM + c16 * 8);
                sv[2 * p]     = gp[0];
                sv[2 * p + 1] = gp[1];
            }
        }

        // ---- MMA: 16 rows x 128 keys, 3 products ----
        float acc[16][4];
        #pragma unroll
        for (int nt = 0; nt < 16; nt++)
            #pragma unroll
            for (int c = 0; c < 4; c++) acc[nt][c] = 0.0f;

        const uint32_t kb = kLane + (uint32_t)(t & 1) * 65536;
        #pragma unroll
        for (int ks = 0; ks < 8; ks++) {
            uint32_t boff = (((uint32_t)(ks * 2 + hib)) ^ xr) << 4;
            uint32_t ah[4], al[4];
            ldsm4(ah, aHbase + boff);
            ldsm4(al, aLbase + boff);
            #pragma unroll
            for (int kg = 0; kg < 8; kg++) {
                uint32_t bh[4], bl[4];
                uint32_t ba = kb + (uint32_t)kg * 4096 + boff;
                ldsm4(bh, ba);
                ldsm4(bl, ba + 32768);
                mma_bf16(acc[2 * kg],     ah, bh[0], bh[2]);
                mma_bf16(acc[2 * kg + 1], ah, bh[1], bh[3]);
                mma_bf16(acc[2 * kg],     ah, bl[0], bl[2]);
                mma_bf16(acc[2 * kg + 1], ah, bl[1], bl[3]);
                mma_bf16(acc[2 * kg],     al, bh[0], bh[2]);
                mma_bf16(acc[2 * kg + 1], al, bh[1], bh[3]);
            }
        }

        // ---- convert + STS next tile into the other buffer ----
        if (t + 1 < NTILES) {
            unsigned char* kd = sm + S_K + ((t + 1) & 1) * 65536;
            #pragma unroll
            for (int p = 0; p < 8; p++) {
                int gidx = p * 256 + tid;
                int row = gidx >> 4, c16 = gidx & 15;
                uint32_t off = (uint32_t)row * 256 + (((uint32_t)c16 ^ (row & 7)) << 4);
                uint4 uh, ul;
                cvt8(sv[2 * p], sv[2 * p + 1], uh, ul);
                *(uint4*)(kd + off) = uh;
                *(uint4*)(kd + 32768 + off) = ul;
            }
        }
        __syncthreads();

        // ---- scan: per-row max, then candidate append (z = 0.5*score) ----
        float m0 = -3.0e38f, m1 = -3.0e38f;
        #pragma unroll
        for (int nt = 0; nt < 16; nt++) {
            m0 = fmaxf(m0, fmaxf(acc[nt][0], acc[nt][1]));
            m1 = fmaxf(m1, fmaxf(acc[nt][2], acc[nt][3]));
        }
        m0 = fmaxf(m0, __shfl_xor_sync(0xffffffffu, m0, 1));
        m0 = fmaxf(m0, __shfl_xor_sync(0xffffffffu, m0, 2));
        m1 = fmaxf(m1, __shfl_xor_sync(0xffffffffu, m1, 1));
        m1 = fmaxf(m1, __shfl_xor_sync(0xffffffffu, m1, 2));
        rmax0 = fmaxf(rmax0, 0.5f * m0);
        rmax1 = fmaxf(rmax1, 0.5f * m1);
        const float thr0 = rmax0 - 1.0f;
        const float thr1 = rmax1 - 1.0f;

        #pragma unroll
        for (int nt = 0; nt < 16; nt++) {
            #pragma unroll
            for (int c = 0; c < 4; c++) {
                float z = 0.5f * acc[nt][c];
                const bool s1 = (c >= 2);
                float thr = s1 ? thr1 : thr0;
                bool pr = z > thr;
                unsigned bal = __ballot_sync(0xffffffffu, pr);
                unsigned bits = (bal >> (g * 4)) & 0xFu;
                if (bits) {
                    int total = __popc(bits);
                    int row = s1 ? row1 : row0;
                    int cnt = s1 ? cnt1 : cnt0;
                    if (cnt + total > CAP) {
                        unsigned qm = 0xFu << (g * 4);
                        if (q == 0) {
                            int wp = 0;
                            for (int i = 0; i < cnt; i++) {
                                float zz = czf[row * CAPP + i];
                                if (zz > thr) {
                                    czf[row * CAPP + wp]  = zz;
                                    cixp[row * CAPP + wp] = cixp[row * CAPP + i];
                                    wp++;
                                }
                            }
                            cnt = wp;
                        }
                        cnt = __shfl_sync(qm, cnt, g * 4);
                    }
                    int pos = cnt + __popc(bits & ((1u << q) - 1u));
                    if (pr && pos < CAP) {
                        czf[row * CAPP + pos]  = z;
                        cixp[row * CAPP + pos] = t * 128 + nt * 8 + q * 2 + (c & 1);
                    }
                    cnt = min(cnt + total, CAP);
                    if (s1) cnt1 = cnt; else cnt0 = cnt;
                }
            }
        }
    }

    if (q == 0) {
        srmx[row0] = rmax0; srmx[row1] = rmax1;
        scnt[row0] = cnt0;  scnt[row1] = cnt1;
    }
    __syncthreads();

    // ---- bisection: thread r (0..127) owns query row r ----
    if (tid < 128) {
        const int r = tid;
        const float zmax = srmx[r];
        const float thr  = zmax - 1.0f;
        const int cnt = scnt[r];
        int c2 = 0;
        for (int i = 0; i < cnt; i++) {
            float zz = czf[r * CAPP + i];
            if (zz > thr) {
                czf[r * CAPP + c2]  = zz;
                cixp[r * CAPP + c2] = cixp[r * CAPP + i];
                c2++;
            }
        }
        float tmin = thr;
        float tmax = zmax - TAUMAX_OFF;
        float tau = 0.5f * (tmin + tmax);
        float Zs  = 1.0f;

        float zr[16];
        const bool inreg = (c2 <= 16);
        if (inreg) {
            #pragma unroll
            for (int i = 0; i < 16; i++)
                zr[i] = (i < c2) ? czf[r * CAPP + i] : -3.0e38f;
        }
        for (int it = 0; it < NITER; it++) {
            tau = 0.5f * (tmin + tmax);
            float Z = 0.0f;
            if (inreg) {
                #pragma unroll
                for (int i = 0; i < 16; i++) {
                    float p = fmaxf(zr[i] - tau, 0.0f);
                    Z = fmaf(p, p, Z);
                }
            } else {
                for (int i = 0; i < c2; i++) {
                    float p = fmaxf(czf[r * CAPP + i] - tau, 0.0f);
                    Z = fmaf(p, p, Z);
                }
            }
            Zs = Z;
            if (Z >= 1.0f) tmin = tau; else tmax = tau;
        }
        const float invZ = 1.0f / Zs;
        for (int i = 0; i < c2; i++) {
            float zz = inreg ? zr[i] : czf[r * CAPP + i];
            float p = fmaxf(zz - tau, 0.0f);
            czf[r * CAPP + i] = p * p * invZ;
        }
        scnt[r] = c2;
    }
    __syncthreads();

    // ---- sparse PV gather: warp per row, lane covers 4 dims ----
    {
        const float4* V4 = (const float4*)(Vg + (size_t)b * SEQ * DIM);
        float4* O4 = (float4*)(Og + ((size_t)b * SEQ + (size_t)qt * MQ) * DIM);
        for (int r = w; r < MQ; r += 8) {
            int c = scnt[r];
            float4 acc = make_float4(0.f, 0.f, 0.f, 0.f);
            for (int i = 0; i < c; i++) {
                float wt = czf[r * CAPP + i];
                int ki   = cixp[r * CAPP + i];
                float4 vv = V4[(size_t)ki * (DIM / 4) + lane];
                acc.x = fmaf(wt, vv.x, acc.x);
                acc.y = fmaf(wt, vv.y, acc.y);
                acc.z = fmaf(wt, vv.z, acc.z);
                acc.w = fmaf(wt, vv.w, acc.w);
            }
            O4[r * (DIM / 4) + lane] = acc;
        }
    }
}

extern "C" void kernel_launch(void* const* d_in, const int* in_sizes, int n_in,
                              void* d_out, int out_size)
{
    const float* Q = (const float*)d_in[0];
    const float* K = (const float*)d_in[1];
    const float* V = (const float*)d_in[2];
    float* O = (float*)d_out;

    cudaFuncSetAttribute(attn_kernel,
                         cudaFuncAttributeMaxDynamicSharedMemorySize, SMEM_TOTAL);
    attn_kernel<<<dim3(SEQ / MQ, BATCH), 256, SMEM_TOTAL>>>(Q, K, V, O);
}

// round 5
// speedup vs baseline: 3.8620x; 1.4796x over previous
#include <cuda_runtime.h>
#include <cuda_bf16.h>
#include <cstdint>

// SparseAttention: QK^T -> entmax(alpha=1.5, 100-iter bisection) -> @V
// B=8, S=2048, D=128 fp32.
//
// Round 5: prep kernel does fp32->bf16 hi/lo split (tile-major linear);
// main kernel: 512 threads, warp tile 16 rows x 64 keys, cp.async K staging
// (double-buffered, swizzled), 3-product bf16 mma.sync with fp32 accum,
// tile-skip candidate scan, exact bisection over candidates, sparse PV.

#define BATCH   8
#define SEQ     2048
#define DIM     128
#define MQ      128
#define NTILES  16
#define TILEB   32768          // 128 x 128 bf16
#define CAPH    16             // candidate slots per (row, key-half)
#define NITER   100
#define TAUMAX_OFF 0.02209708691f   // float32(2048^-0.5)

// ---- prep output: bf16 hi/lo, tile-major [b][tile][row][128] ----
__device__ __align__(16) unsigned char g_Qhi[BATCH * NTILES * TILEB];
__device__ __align__(16) unsigned char g_Qlo[BATCH * NTILES * TILEB];
__device__ __align__(16) unsigned char g_Khi[BATCH * NTILES * TILEB];
__device__ __align__(16) unsigned char g_Klo[BATCH * NTILES * TILEB];

// ---- smem layout (bytes) ----
#define S_QHI   0               // 32768 (lo at +32768)
#define S_K     65536           // 2 bufs x (hi 32768 + lo 32768)
#define S_CZ    196608          // float cz[128][32]  (two 16-slot halves)
#define S_CIX   212992          // int   cix[128][32]
#define S_RMX   229376          // float rmax[128][2]
#define S_CNT   230400          // int   cnt[128][2]
#define SMEM_TOTAL 231424

__device__ __forceinline__ uint32_t smem_u32(const void* p) {
    uint32_t a;
    asm("{ .reg .u64 t; cvta.to.shared.u64 t, %1; cvt.u32.u64 %0, t; }"
        : "=r"(a) : "l"(p));
    return a;
}
__device__ __forceinline__ void cp16(uint32_t dst, const void* src) {
    asm volatile("cp.async.cg.shared.global [%0], [%1], 16;"
                 :: "r"(dst), "l"(src) : "memory");
}
#define CP_COMMIT() asm volatile("cp.async.commit_group;" ::: "memory")
#define CP_WAIT0()  asm volatile("cp.async.wait_group 0;" ::: "memory")

__device__ __forceinline__ void ldsm4(uint32_t* r, uint32_t addr) {
    asm volatile("ldmatrix.sync.aligned.m8n8.x4.shared.b16 {%0,%1,%2,%3}, [%4];"
                 : "=r"(r[0]), "=r"(r[1]), "=r"(r[2]), "=r"(r[3]) : "r"(addr));
}
__device__ __forceinline__ void mma_bf16(float* d, const uint32_t* a,
                                         uint32_t b0, uint32_t b1) {
    asm volatile(
        "mma.sync.aligned.m16n8k16.row.col.f32.bf16.bf16.f32 "
        "{%0,%1,%2,%3}, {%4,%5,%6,%7}, {%8,%9}, {%0,%1,%2,%3};"
        : "+f"(d[0]), "+f"(d[1]), "+f"(d[2]), "+f"(d[3])
        : "r"(a[0]), "r"(a[1]), "r"(a[2]), "r"(a[3]), "r"(b0), "r"(b1));
}

// ================= prep kernel =================
__global__ __launch_bounds__(256)
void prep_kernel(const float* __restrict__ Qg, const float* __restrict__ Kg)
{
    int idx = blockIdx.x * 256 + threadIdx.x;     // [0, 262144)
    const float* src = blockIdx.y ? Kg : Qg;
    unsigned char* dhi = blockIdx.y ? g_Khi : g_Qhi;
    unsigned char* dlo = blockIdx.y ? g_Klo : g_Qlo;

    int c8   = idx & 15;
    int rowg = (idx >> 4) & 2047;
    int b    = idx >> 15;

    const float4* p = (const float4*)(src + ((size_t)(b * SEQ + rowg) * DIM + c8 * 8));
    float4 v0 = p[0], v1 = p[1];
    float x[8] = {v0.x, v0.y, v0.z, v0.w, v1.x, v1.y, v1.z, v1.w};

    uint32_t h[8], l[8];
    #pragma unroll
    for (int j = 0; j < 8; j++) {
        __nv_bfloat16 hb = __float2bfloat16(x[j]);
        float r = x[j] - __bfloat162float(hb);
        __nv_bfloat16 lb = __float2bfloat16(r);
        h[j] = (uint32_t)__bfloat16_as_ushort(hb);
        l[j] = (uint32_t)__bfloat16_as_ushort(lb);
    }
    uint4 uh, ul;
    uh.x = h[0] | (h[1] << 16); uh.y = h[2] | (h[3] << 16);
    uh.z = h[4] | (h[5] << 16); uh.w = h[6] | (h[7] << 16);
    ul.x = l[0] | (l[1] << 16); ul.y = l[2] | (l[3] << 16);
    ul.z = l[4] | (l[5] << 16); ul.w = l[6] | (l[7] << 16);

    // tile-major: [b][tile][row][c]
    size_t base = (size_t)(b * NTILES + (rowg >> 7)) * TILEB
                + (size_t)(rowg & 127) * 256 + (size_t)c8 * 16;
    *(uint4*)(dhi + base) = uh;
    *(uint4*)(dlo + base) = ul;
}

// load one 32KB half-pair (hi+lo) with swizzle, 512 threads, 8 cp.async each
__device__ __forceinline__ void stage_tile(uint32_t sdst, const unsigned char* ghi,
                                           const unsigned char* glo, int tid) {
    #pragma unroll
    for (int p = 0; p < 4; p++) {
        int gidx = p * 512 + tid;          // 0..2047
        int row = gidx >> 4, c16 = gidx & 15;
        uint32_t off = (uint32_t)row * 256 + (((uint32_t)c16 ^ (row & 7)) << 4);
        cp16(sdst + off,         ghi + (size_t)gidx * 16);
        cp16(sdst + 32768 + off, glo + (size_t)gidx * 16);
    }
}

// ================= main kernel =================
__global__ __launch_bounds__(512, 1)
void attn_kernel(const float* __restrict__ Vg, float* __restrict__ Og)
{
    extern __shared__ unsigned char sm[];
    const uint32_t sbase = smem_u32(sm);
    const int tid  = threadIdx.x;
    const int lane = tid & 31;
    const int w    = tid >> 5;          // 16 warps
    const int wm   = w & 7;             // row block
    const int half = w >> 3;            // key half
    const int b    = blockIdx.y;
    const int qt   = blockIdx.x;

    // ---- prologue: stage Q (hi/lo) and K tile 0 ----
    {
        size_t qb = (size_t)(b * NTILES + qt) * TILEB;
        stage_tile(sbase + S_QHI, g_Qhi + qb, g_Qlo + qb, tid);
        size_t kb = (size_t)(b * NTILES) * TILEB;
        stage_tile(sbase + S_K, g_Khi + kb, g_Klo + kb, tid);
        CP_COMMIT();
        CP_WAIT0();
    }
    __syncthreads();

    const int g  = lane >> 2;
    const int q  = lane & 3;
    const int rterm = (((lane >> 3) & 1) << 3) + (lane & 7);
    const int hib = lane >> 4;
    const int xr  = lane & 7;
    const unsigned qm = 0xFu << (g * 4);
    const uint32_t aHbase = sbase + S_QHI + (uint32_t)(wm * 16 + rterm) * 256;
    const uint32_t aLbase = aHbase + 32768;
    const uint32_t kLane  = sbase + S_K + (uint32_t)rterm * 256;

    float* czf  = (float*)(sm + S_CZ);
    int*   cixp = (int*)(sm + S_CIX);
    float* srmx = (float*)(sm + S_RMX);
    int*   scnt = (int*)(sm + S_CNT);

    const int row0 = wm * 16 + g, row1 = row0 + 8;
    const int slot0 = row0 * 32 + half * CAPH;
    const int slot1 = row1 * 32 + half * CAPH;
    float rmax0 = -3.0e38f, rmax1 = -3.0e38f;
    int cnt0 = 0, cnt1 = 0;

    for (int t = 0; t < NTILES; t++) {
        // ---- issue cp.async for next tile ----
        if (t + 1 < NTILES) {
            size_t kb = (size_t)(b * NTILES + t + 1) * TILEB;
            stage_tile(sbase + S_K + (uint32_t)((t + 1) & 1) * 65536,
                       g_Khi + kb, g_Klo + kb, tid);
        }
        CP_COMMIT();

        // ---- MMA: 16 rows x 64 keys, 3 products ----
        float acc[8][4];
        #pragma unroll
        for (int nt = 0; nt < 8; nt++)
            #pragma unroll
            for (int c = 0; c < 4; c++) acc[nt][c] = 0.0f;

        const uint32_t kb = kLane + (uint32_t)(t & 1) * 65536;
        #pragma unroll
        for (int ks = 0; ks < 8; ks++) {
            uint32_t boff = (((uint32_t)(ks * 2 + hib)) ^ xr) << 4;
            uint32_t ah[4], al[4];
            ldsm4(ah, aHbase + boff);
            ldsm4(al, aLbase + boff);
            #pragma unroll
            for (int kg = 0; kg < 4; kg++) {
                uint32_t bh[4], bl[4];
                uint32_t ba = kb + (uint32_t)(half * 4 + kg) * 4096 + boff;
                ldsm4(bh, ba);
                ldsm4(bl, ba + 32768);
                mma_bf16(acc[2 * kg],     ah, bh[0], bh[2]);
                mma_bf16(acc[2 * kg + 1], ah, bh[1], bh[3]);
                mma_bf16(acc[2 * kg],     ah, bl[0], bl[2]);
                mma_bf16(acc[2 * kg + 1], ah, bl[1], bl[3]);
                mma_bf16(acc[2 * kg],     al, bh[0], bh[2]);
                mma_bf16(acc[2 * kg + 1], al, bh[1], bh[3]);
            }
        }

        // ---- scan: tile max per row, skip if no candidate possible ----
        float m0 = -3.0e38f, m1 = -3.0e38f;
        #pragma unroll
        for (int nt = 0; nt < 8; nt++) {
            m0 = fmaxf(m0, fmaxf(acc[nt][0], acc[nt][1]));
            m1 = fmaxf(m1, fmaxf(acc[nt][2], acc[nt][3]));
        }
        m0 = fmaxf(m0, __shfl_xor_sync(0xffffffffu, m0, 1));
        m0 = fmaxf(m0, __shfl_xor_sync(0xffffffffu, m0, 2));
        m1 = fmaxf(m1, __shfl_xor_sync(0xffffffffu, m1, 1));
        m1 = fmaxf(m1, __shfl_xor_sync(0xffffffffu, m1, 2));
        const float z0max = 0.5f * m0, z1max = 0.5f * m1;
        rmax0 = fmaxf(rmax0, z0max);
        rmax1 = fmaxf(rmax1, z1max);
        const float thr0 = rmax0 - 1.0f;
        const float thr1 = rmax1 - 1.0f;
        const int kbase = t * 128 + half * 64;

        if (z0max > thr0) {   // quad-uniform
            #pragma unroll
            for (int nt = 0; nt < 8; nt++) {
                #pragma unroll
                for (int c = 0; c < 2; c++) {
                    float z = 0.5f * acc[nt][c];
                    bool pr = z > thr0;
                    unsigned bal = __ballot_sync(qm, pr);
                    unsigned bits = (bal >> (g * 4)) & 0xFu;
                    if (bits) {
                        int total = __popc(bits);
                        if (cnt0 + total > CAPH) {
                            if (q == 0) {
                                int wp = 0;
                                for (int i = 0; i < cnt0; i++) {
                                    float zz = czf[slot0 + i];
                                    if (zz > thr0) {
                                        czf[slot0 + wp]  = zz;
                                        cixp[slot0 + wp] = cixp[slot0 + i];
                                        wp++;
                                    }
                                }
                                cnt0 = wp;
                            }
                            cnt0 = __shfl_sync(qm, cnt0, g * 4);
                        }
                        int pos = cnt0 + __popc(bits & ((1u << q) - 1u));
                        if (pr && pos < CAPH) {
                            czf[slot0 + pos]  = z;
                            cixp[slot0 + pos] = kbase + nt * 8 + q * 2 + c;
                        }
                        cnt0 = min(cnt0 + total, CAPH);
                    }
                }
            }
        }
        if (z1max > thr1) {
            #pragma unroll
            for (int nt = 0; nt < 8; nt++) {
                #pragma unroll
                for (int c = 2; c < 4; c++) {
                    float z = 0.5f * acc[nt][c];
                    bool pr = z > thr1;
                    unsigned bal = __ballot_sync(qm, pr);
                    unsigned bits = (bal >> (g * 4)) & 0xFu;
                    if (bits) {
                        int total = __popc(bits);
                        if (cnt1 + total > CAPH) {
                            if (q == 0) {
                                int wp = 0;
                                for (int i = 0; i < cnt1; i++) {
                                    float zz = czf[slot1 + i];
                                    if (zz > thr1) {
                                        czf[slot1 + wp]  = zz;
                                        cixp[slot1 + wp] = cixp[slot1 + i];
                                        wp++;
                                    }
                                }
                                cnt1 = wp;
                            }
                            cnt1 = __shfl_sync(qm, cnt1, g * 4);
                        }
                        int pos = cnt1 + __popc(bits & ((1u << q) - 1u));
                        if (pr && pos < CAPH) {
                            czf[slot1 + pos]  = z;
                            cixp[slot1 + pos] = kbase + nt * 8 + q * 2 + (c & 1);
                        }
                        cnt1 = min(cnt1 + total, CAPH);
                    }
                }
            }
        }

        CP_WAIT0();
        __syncthreads();
    }

    if (q == 0) {
        srmx[row0 * 2 + half] = rmax0;
        srmx[row1 * 2 + half] = rmax1;
        scnt[row0 * 2 + half] = cnt0;
        scnt[row1 * 2 + half] = cnt1;
    }
    __syncthreads();

    // ---- bisection: thread r (0..127) owns row r; merge both halves ----
    if (tid < 128) {
        const int r = tid;
        const float zmax = fmaxf(srmx[r * 2], srmx[r * 2 + 1]);
        const float thr  = zmax - 1.0f;
        int c2 = 0;
        #pragma unroll
        for (int h = 0; h < 2; h++) {
            int cn = scnt[r * 2 + h];
            for (int i = 0; i < cn; i++) {
                float zz = czf[r * 32 + h * CAPH + i];
                if (zz > thr) {
                    czf[r * 32 + c2]  = zz;
                    cixp[r * 32 + c2] = cixp[r * 32 + h * CAPH + i];
                    c2++;
                }
            }
        }
        float tmin = thr;
        float tmax = zmax - TAUMAX_OFF;
        float tau = 0.5f * (tmin + tmax);
        float Zs  = 1.0f;

        float zr[16];
        const bool inreg = (c2 <= 16);
        if (inreg) {
            #pragma unroll
            for (int i = 0; i < 16; i++)
                zr[i] = (i < c2) ? czf[r * 32 + i] : -3.0e38f;
        }
        for (int it = 0; it < NITER; it++) {
            tau = 0.5f * (tmin + tmax);
            float Z = 0.0f;
            if (inreg) {
                #pragma unroll
                for (int i = 0; i < 16; i++) {
                    float p = fmaxf(zr[i] - tau, 0.0f);
                    Z = fmaf(p, p, Z);
                }
            } else {
                for (int i = 0; i < c2; i++) {
                    float p = fmaxf(czf[r * 32 + i] - tau, 0.0f);
                    Z = fmaf(p, p, Z);
                }
            }
            Zs = Z;
            if (Z >= 1.0f) tmin = tau; else tmax = tau;
        }
        const float invZ = 1.0f / Zs;
        for (int i = 0; i < c2; i++) {
            float zz = inreg ? zr[i] : czf[r * 32 + i];
            float p = fmaxf(zz - tau, 0.0f);
            czf[r * 32 + i] = p * p * invZ;
        }
        scnt[r * 2] = c2;
    }
    __syncthreads();

    // ---- sparse PV gather: warp per row, lane covers 4 dims ----
    {
        const float4* V4 = (const float4*)(Vg + (size_t)b * SEQ * DIM);
        float4* O4 = (float4*)(Og + ((size_t)b * SEQ + (size_t)qt * MQ) * DIM);
        for (int r = w; r < MQ; r += 16) {
            int c = scnt[r * 2];
            float4 acc = make_float4(0.f, 0.f, 0.f, 0.f);
            for (int i = 0; i < c; i++) {
                float wt = czf[r * 32 + i];
                int ki   = cixp[r * 32 + i];
                float4 vv = V4[(size_t)ki * (DIM / 4) + lane];
                acc.x = fmaf(wt, vv.x, acc.x);
                acc.y = fmaf(wt, vv.y, acc.y);
                acc.z = fmaf(wt, vv.z, acc.z);
                acc.w = fmaf(wt, vv.w, acc.w);
            }
            O4[r * (DIM / 4) + lane] = acc;
        }
    }
}

extern "C" void kernel_launch(void* const* d_in, const int* in_sizes, int n_in,
                              void* d_out, int out_size)
{
    const float* Q = (const float*)d_in[0];
    const float* K = (const float*)d_in[1];
    const float* V = (const float*)d_in[2];
    float* O = (float*)d_out;

    prep_kernel<<<dim3(1024, 2), 256>>>(Q, K);

    cudaFuncSetAttribute(attn_kernel,
                         cudaFuncAttributeMaxDynamicSharedMemorySize, SMEM_TOTAL);
    attn_kernel<<<dim3(SEQ / MQ, BATCH), 512, SMEM_TOTAL>>>(V, O);
}